// round 2
// baseline (speedup 1.0000x reference)
#include <cuda_runtime.h>
#include <stdint.h>

// AUC over sigmoid(output), 30 uniform thresholds.
// Single fused kernel: 31-bin histogram (all elems + true-class elems),
// last block finalizes the trapezoid area and re-zeros globals for the
// next graph replay.

#define NROWS   500000
#define NCOLS   64
#define NELEM   (NROWS * NCOLS)        // 32,000,000
#define NF4     (NELEM / 4)            // 8,000,000
#define NBINS   31
#define BLOCK   256
#define NBLK    592                    // 4 blocks/SM * 148 SMs
#define T       (NBLK * BLOCK)         // 151,552 threads

__device__ unsigned int g_hist_all[32];   // zero-init at load; re-zeroed per run
__device__ unsigned int g_hist_t[32];
__device__ unsigned int g_done;

// bin = floor(30 * sigmoid(x)), in 0..30.
__device__ __forceinline__ int bin_of(float x) {
    float t = x * -1.4426950408889634f;
    float e;
    asm("ex2.approx.f32 %0, %1;" : "=f"(e) : "f"(t));     // e^-x
    float d = e + 1.0f;
    float v;
    asm("rcp.approx.f32 %0, %1;" : "=f"(v) : "f"(d));     // sigmoid in (0,1]
    float z = fmaf(v, 30.0f, -0.5f);                       // (-0.5, 29.5]
    float y = z + 12582912.0f;                             // +1.5*2^23 -> RN = floor(30v)
    return __float_as_int(y) - 0x4B400000;
}

__global__ __launch_bounds__(BLOCK, 4)
void auc_kernel(const float4* __restrict__ o4, const int* __restrict__ tgt,
                float* __restrict__ out) {
    // 4 independent byte-counter sub-histograms -> the 4 unrolled float4s'
    // RMW chains don't alias each other. h8[k][b][tid]. 31,744 B.
    __shared__ unsigned char h8[4 * NBINS * BLOCK];
    __shared__ unsigned int  strue[32];
    __shared__ int           s_last;

    const int tid = threadIdx.x;

    unsigned int* hw = (unsigned int*)h8;
    #pragma unroll
    for (int i = tid; i < 4 * NBINS * BLOCK / 4; i += BLOCK) hw[i] = 0u;
    if (tid < 32) strue[tid] = 0u;
    __syncthreads();

    int i0 = blockIdx.x * BLOCK + tid;

    // ---- main loop: 4 float4s per mega-iter, loads front-batched (MLP>=5) ----
    while (i0 + 3 * T < NF4) {
        int f0 = i0, f1 = i0 + T, f2 = i0 + 2 * T, f3 = i0 + 3 * T;
        float4 v0 = __ldg(o4 + f0);
        float4 v1 = __ldg(o4 + f1);
        float4 v2 = __ldg(o4 + f2);
        float4 v3 = __ldg(o4 + f3);
        int tg0 = __ldg(tgt + (f0 >> 4));
        int tg1 = __ldg(tgt + (f1 >> 4));
        int tg2 = __ldg(tgt + (f2 >> 4));
        int tg3 = __ldg(tgt + (f3 >> 4));

        #pragma unroll
        for (int k = 0; k < 4; k++) {
            float4 x = (k == 0) ? v0 : (k == 1) ? v1 : (k == 2) ? v2 : v3;
            int    f = (k == 0) ? f0 : (k == 1) ? f1 : (k == 2) ? f2 : f3;
            int    tg = (k == 0) ? tg0 : (k == 1) ? tg1 : (k == 2) ? tg2 : tg3;
            unsigned char* r = &h8[k * NBINS * BLOCK + tid];
            int b0 = bin_of(x.x), b1 = bin_of(x.y), b2 = bin_of(x.z), b3 = bin_of(x.w);
            r[b0 * BLOCK]++;
            r[b1 * BLOCK]++;
            r[b2 * BLOCK]++;
            r[b3 * BLOCK]++;
            if ((tg >> 2) == (f & 15)) {
                int j = tg & 3;
                int bb = (j & 2) ? ((j & 1) ? b3 : b2) : ((j & 1) ? b1 : b0);
                atomicAdd(&strue[bb], 1u);
            }
        }
        i0 += 4 * T;
    }
    // ---- tail: at most 3 single-float4 iterations, into region 0 ----
    while (i0 < NF4) {
        float4 x = __ldg(o4 + i0);
        int tg = __ldg(tgt + (i0 >> 4));
        unsigned char* r = &h8[tid];
        int b0 = bin_of(x.x), b1 = bin_of(x.y), b2 = bin_of(x.z), b3 = bin_of(x.w);
        r[b0 * BLOCK]++;
        r[b1 * BLOCK]++;
        r[b2 * BLOCK]++;
        r[b3 * BLOCK]++;
        if ((tg >> 2) == (i0 & 15)) {
            int j = tg & 3;
            int bb = (j & 2) ? ((j & 1) ? b3 : b2) : ((j & 1) ? b1 : b0);
            atomicAdd(&strue[bb], 1u);
        }
        i0 += T;
    }
    __syncthreads();

    // ---- block reduction: dp4a over packed byte counters ----
    const unsigned int* w = (const unsigned int*)h8;   // word idx: k*1984 + b*64 + t/4
    int lane = tid & 31, wid = tid >> 5;               // 8 warps
    for (int b = wid; b < NBINS; b += (BLOCK / 32)) {
        unsigned int s = 0;
        #pragma unroll
        for (int k = 0; k < 4; k++) {
            #pragma unroll
            for (int i = 0; i < 2; i++) {              // 64 words per (k,b)
                unsigned int word = w[k * (NBINS * BLOCK / 4) + b * (BLOCK / 4) + i * 32 + lane];
                s = __dp4a(word, 0x01010101u, s);
            }
        }
        #pragma unroll
        for (int o = 16; o; o >>= 1) s += __shfl_down_sync(0xffffffffu, s, o);
        if (lane == 0 && s) atomicAdd(&g_hist_all[b], s);
    }
    if (tid < NBINS) {
        unsigned int s = strue[tid];
        if (s) atomicAdd(&g_hist_t[tid], s);
    }

    // ---- last-block finalize ----
    if (tid == 0) {
        __threadfence();
        unsigned int prev = atomicAdd(&g_done, 1u);
        s_last = (prev == gridDim.x - 1);
    }
    __syncthreads();
    if (s_last && tid == 0) {
        __threadfence();
        volatile unsigned int* vha = g_hist_all;
        volatile unsigned int* vht = g_hist_t;
        double ht[NBINS], ha[NBINS], trues = 0.0;
        for (int b = 0; b < NBINS; b++) {
            ht[b] = (double)vht[b];
            ha[b] = (double)vha[b];
            trues += ht[b];
        }
        double falses = (double)NELEM - trues;

        double tp_asc[30], fp_asc[30], ct = 0.0, cf = 0.0;
        for (int j = 0; j < 30; j++) {
            ct += ht[j];
            cf += (ha[j] - ht[j]);
            tp_asc[j] = trues  - ct;
            fp_asc[j] = falses - cf;
        }
        const double eps = 1e-8;
        double area = 0.0, pt = 0.0, pf = 0.0;
        for (int i = 0; i < 30; i++) {
            double tpr = tp_asc[29 - i] / (trues  + eps);
            double fpr = fp_asc[29 - i] / (falses + eps);
            double wdt = fabs(fpr - pf);
            double mn = fmin(tpr, pt), mx = fmax(tpr, pt);
            area += wdt * mn + 0.5 * wdt * (mx - mn);
            pt = tpr; pf = fpr;
        }
        out[0] = (float)area;

        // reset for next graph replay
        for (int b = 0; b < 32; b++) { g_hist_all[b] = 0u; g_hist_t[b] = 0u; }
        g_done = 0u;
    }
}

extern "C" void kernel_launch(void* const* d_in, const int* in_sizes, int n_in,
                              void* d_out, int out_size) {
    const float* output = (const float*)d_in[0];
    const int*   target = (const int*)d_in[1];
    if (n_in >= 2 && in_sizes[0] == NROWS && in_sizes[1] == NELEM) {
        output = (const float*)d_in[1];
        target = (const int*)d_in[0];
    }
    auc_kernel<<<NBLK, BLOCK>>>((const float4*)output, target, (float*)d_out);
}

// round 4
// speedup vs baseline: 1.2091x; 1.2091x over previous
#include <cuda_runtime.h>
#include <stdint.h>

// AUC over sigmoid(output), 30 uniform thresholds. Single fused kernel.
// Word-counter per-thread private histogram (conflict-free), 4-deep
// front-batched float4 loads for MLP, last-block finalize.

#define NROWS   500000
#define NCOLS   64
#define NELEM   (NROWS * NCOLS)        // 32,000,000
#define NF4     (NELEM / 4)            // 8,000,000
#define NBINS   31
#define BLOCK   256
#define BPSM    5
#define NBLK    (148 * BPSM)           // 740
#define T       (NBLK * BLOCK)         // 189,440

__device__ unsigned int g_hist_all[32];   // zero-init; re-zeroed each run
__device__ unsigned int g_hist_t[32];
__device__ unsigned int g_done;

// bin = floor(30 * sigmoid(x)), in 0..30.
__device__ __forceinline__ int bin_of(float x) {
    float t = x * -1.4426950408889634f;
    float e;
    asm("ex2.approx.f32 %0, %1;" : "=f"(e) : "f"(t));     // e^-x
    float d = e + 1.0f;
    float v;
    asm("rcp.approx.f32 %0, %1;" : "=f"(v) : "f"(d));     // sigmoid in (0,1]
    float z = fmaf(v, 30.0f, -0.5f);                       // (-0.5, 29.5]
    float y = z + 12582912.0f;                             // +1.5*2^23 -> RN = floor
    return __float_as_int(y) - 0x4B400000;
}

__device__ __forceinline__ void hist4(unsigned int* __restrict__ hrow,
                                      float4 x, int f, int tg,
                                      unsigned int* __restrict__ strue) {
    int b0 = bin_of(x.x), b1 = bin_of(x.y), b2 = bin_of(x.z), b3 = bin_of(x.w);
    hrow[b0 * BLOCK]++;
    hrow[b1 * BLOCK]++;
    hrow[b2 * BLOCK]++;
    hrow[b3 * BLOCK]++;
    if ((tg >> 2) == (f & 15)) {                 // this float4 holds the true col
        int j = tg & 3;
        int bb = (j & 2) ? ((j & 1) ? b3 : b2) : ((j & 1) ? b1 : b0);
        atomicAdd(&strue[bb], 1u);
    }
}

__global__ __launch_bounds__(BLOCK, BPSM)
void auc_kernel(const float4* __restrict__ o4, const int* __restrict__ tgt,
                float* __restrict__ out) {
    __shared__ unsigned int hist[NBINS * BLOCK];   // 31,744 B, bank-conflict-free
    __shared__ unsigned int strue[32];
    __shared__ int s_last;

    const int tid = threadIdx.x;
    #pragma unroll
    for (int i = tid; i < NBINS * BLOCK; i += BLOCK) hist[i] = 0u;
    if (tid < 32) strue[tid] = 0u;
    __syncthreads();

    unsigned int* hrow = &hist[tid];
    int i0 = blockIdx.x * BLOCK + tid;

    // main loop: 4 float4s per mega-iter, loads front-batched
    while (i0 + 3 * T < NF4) {
        int f0 = i0, f1 = i0 + T, f2 = i0 + 2 * T, f3 = i0 + 3 * T;
        float4 v0 = __ldg(o4 + f0);
        float4 v1 = __ldg(o4 + f1);
        float4 v2 = __ldg(o4 + f2);
        float4 v3 = __ldg(o4 + f3);
        int tg0 = __ldg(tgt + (f0 >> 4));
        int tg1 = __ldg(tgt + (f1 >> 4));
        int tg2 = __ldg(tgt + (f2 >> 4));
        int tg3 = __ldg(tgt + (f3 >> 4));

        hist4(hrow, v0, f0, tg0, strue);
        hist4(hrow, v1, f1, tg1, strue);
        hist4(hrow, v2, f2, tg2, strue);
        hist4(hrow, v3, f3, tg3, strue);
        i0 += 4 * T;
    }
    // tail
    while (i0 < NF4) {
        float4 x = __ldg(o4 + i0);
        int tg = __ldg(tgt + (i0 >> 4));
        hist4(hrow, x, i0, tg, strue);
        i0 += T;
    }
    __syncthreads();

    // block reduction -> global atomics
    int lane = tid & 31, wid = tid >> 5;           // 8 warps
    for (int b = wid; b < NBINS; b += (BLOCK / 32)) {
        unsigned int s = 0;
        #pragma unroll
        for (int k = 0; k < BLOCK / 32; k++) s += hist[b * BLOCK + k * 32 + lane];
        #pragma unroll
        for (int o = 16; o; o >>= 1) s += __shfl_down_sync(0xffffffffu, s, o);
        if (lane == 0 && s) atomicAdd(&g_hist_all[b], s);
    }
    if (tid < NBINS) {
        unsigned int s = strue[tid];
        if (s) atomicAdd(&g_hist_t[tid], s);
    }

    // last-block finalize
    if (tid == 0) {
        __threadfence();
        unsigned int prev = atomicAdd(&g_done, 1u);
        s_last = (prev == gridDim.x - 1);
    }
    __syncthreads();
    if (s_last && tid == 0) {
        __threadfence();
        volatile unsigned int* vha = g_hist_all;
        volatile unsigned int* vht = g_hist_t;
        double ht[NBINS], ha[NBINS], trues = 0.0;
        for (int b = 0; b < NBINS; b++) {
            ht[b] = (double)vht[b];
            ha[b] = (double)vha[b];
            trues += ht[b];
        }
        double falses = (double)NELEM - trues;

        double tp_asc[30], fp_asc[30], ct = 0.0, cf = 0.0;
        for (int j = 0; j < 30; j++) {
            ct += ht[j];
            cf += (ha[j] - ht[j]);
            tp_asc[j] = trues  - ct;
            fp_asc[j] = falses - cf;
        }
        const double eps = 1e-8;
        double area = 0.0, pt = 0.0, pf = 0.0;
        for (int i = 0; i < 30; i++) {
            double tpr = tp_asc[29 - i] / (trues  + eps);
            double fpr = fp_asc[29 - i] / (falses + eps);
            double wdt = fabs(fpr - pf);
            double mn = fmin(tpr, pt), mx = fmax(tpr, pt);
            area += wdt * mn + 0.5 * wdt * (mx - mn);
            pt = tpr; pf = fpr;
        }
        out[0] = (float)area;

        for (int b = 0; b < 32; b++) { g_hist_all[b] = 0u; g_hist_t[b] = 0u; }
        g_done = 0u;
    }
}

extern "C" void kernel_launch(void* const* d_in, const int* in_sizes, int n_in,
                              void* d_out, int out_size) {
    const float* output = (const float*)d_in[0];
    const int*   target = (const int*)d_in[1];
    if (n_in >= 2 && in_sizes[0] == NROWS && in_sizes[1] == NELEM) {
        output = (const float*)d_in[1];
        target = (const int*)d_in[0];
    }
    auc_kernel<<<NBLK, BLOCK>>>((const float4*)output, target, (float*)d_out);
}